// round 8
// baseline (speedup 1.0000x reference)
#include <cuda_runtime.h>
#include <cstdint>

#define Bb 8
#define Tt 2048
#define Vv 1024
#define BM 128
#define BN 256
#define BK 32
#define NTH 256
#define BUFB 49152   // A tile 16KB + B tile 32KB

// ---- scratch (static __device__ — no allocations allowed) ----
__device__ float g_WkT[Vv * Vv];
__device__ float g_WqT[Vv * Vv];
__device__ float g_WvT[Vv * Vv];
__device__ float g_pv[Tt];
__device__ float g_CT[Vv * Vv];                 // CT[i][a] = (Wq^T Wk)[a][i]
__device__ float g_Cg[(size_t)Bb * Vv * Tt];    // Cg[b][a][s'] = CT[idx[b][s']][a]
__device__ float g_Gv[(size_t)Bb * Vv * Tt];    // Gv[b][o][s]  = WvT[idx[b][s]][o]
__device__ float g_Ah[(size_t)Bb * Vv * Tt];    // Ah[b][a][s]

// ---------------- helpers ----------------
__device__ __forceinline__ uint32_t smem_u32(const void* p) {
    uint32_t a;
    asm("{ .reg .u64 t; cvta.to.shared.u64 t, %1; cvt.u32.u64 %0, t; }" : "=r"(a) : "l"(p));
    return a;
}
__device__ __forceinline__ float tf32r(float x) {
    unsigned u;
    asm("cvt.rna.tf32.f32 %0, %1;" : "=r"(u) : "f"(x));
    return __uint_as_float(u);
}
__device__ __forceinline__ void cpa16(uint32_t dst, const void* src) {
    asm volatile("cp.async.cg.shared.global [%0], [%1], 16;" :: "r"(dst), "l"(src) : "memory");
}
#define CP_COMMIT() asm volatile("cp.async.commit_group;" ::: "memory")
#define CP_WAIT1()  asm volatile("cp.async.wait_group 1;" ::: "memory")
#define CP_WAIT0()  asm volatile("cp.async.wait_group 0;" ::: "memory")

__device__ __forceinline__ void mma_tf32(float* c, const float* a, float b0, float b1) {
    asm volatile(
        "mma.sync.aligned.m16n8k8.row.col.f32.tf32.tf32.f32 "
        "{%0,%1,%2,%3}, {%4,%5,%6,%7}, {%8,%9}, {%0,%1,%2,%3};"
        : "+f"(c[0]), "+f"(c[1]), "+f"(c[2]), "+f"(c[3])
        : "r"(__float_as_uint(a[0])), "r"(__float_as_uint(a[1])),
          "r"(__float_as_uint(a[2])), "r"(__float_as_uint(a[3])),
          "r"(__float_as_uint(b0)), "r"(__float_as_uint(b1)));
}

// ---------------- MMA core: one BK=32 chunk, warp tile 64x64 ----------------
// Tile layout [row][k], 128B rows, swizzle folded into ko[] (bank-conflict-free).
__device__ __forceinline__ void mma_chunk(const char* Atp, const char* Btp,
                                          const uint32_t* ko, float acc[4][8][4]) {
#pragma unroll
    for (int k8 = 0; k8 < 4; k8++) {
        const char* a0p = Atp + ko[k8 * 2 + 0];
        const char* a1p = Atp + ko[k8 * 2 + 1];
        const char* b0p = Btp + ko[k8 * 2 + 0];
        const char* b1p = Btp + ko[k8 * 2 + 1];
        float a[4][4];
#pragma unroll
        for (int mf = 0; mf < 4; mf++) {
            a[mf][0] = *(const float*)(a0p + mf * 2048);
            a[mf][1] = *(const float*)(a0p + mf * 2048 + 1024);
            a[mf][2] = *(const float*)(a1p + mf * 2048);
            a[mf][3] = *(const float*)(a1p + mf * 2048 + 1024);
        }
#pragma unroll
        for (int nf = 0; nf < 8; nf++) {
            const float b0 = *(const float*)(b0p + nf * 1024);
            const float b1 = *(const float*)(b1p + nf * 1024);
#pragma unroll
            for (int mf = 0; mf < 4; mf++)
                mma_tf32(acc[mf][nf], a[mf], b0, b1);
        }
    }
}

// 8 warps: wm in {0,64} (2), wn in {0,64,128,192} (4)
#define GEMM_PROLOG() \
    extern __shared__ char dsm[]; \
    const int tid = threadIdx.x; \
    const int wid = tid >> 5, lane = tid & 31; \
    const int gid = lane >> 2, kq = lane & 3; \
    const int wm = (wid & 1) * 64, wn = (wid >> 1) * 64; \
    uint32_t ko[8]; \
    { const uint32_t xg = (uint32_t)(gid & 7) << 4; \
      _Pragma("unroll") for (int k8 = 0; k8 < 4; k8++) \
      _Pragma("unroll") for (int h = 0; h < 2; h++) \
          ko[k8 * 2 + h] = ((uint32_t)((k8 * 8 + kq + h * 4) * 4)) ^ xg; } \
    const char* Abase = dsm + (wm + gid) * 128; \
    const char* Bbase = dsm + 16384 + (wn + gid) * 128; \
    const uint32_t smem0 = smem_u32(dsm); \
    const int rowA = tid >> 1; \
    const int chA0 = (tid & 1) * 4; \
    const uint32_t offA = (uint32_t)rowA * 128; \
    const uint32_t fxA = (uint32_t)(rowA & 7) << 4; \
    const uint32_t offB = 16384u + (uint32_t)tid * 128; \
    const uint32_t fxB = (uint32_t)(tid & 7) << 4; \
    float acc[4][8][4]; \
    _Pragma("unroll") for (int mf = 0; mf < 4; mf++) \
    _Pragma("unroll") for (int nf = 0; nf < 8; nf++) \
    _Pragma("unroll") for (int c = 0; c < 4; c++) acc[mf][nf][c] = 0.f;

// triple-buffered mainloop: fill 2 ahead, one sync per chunk
#define GEMM_LOOP(nt, FILL) \
    FILL(0, 0u); CP_COMMIT(); \
    FILL(1, (uint32_t)BUFB); CP_COMMIT(); \
    { int p = 0; \
      for (int kt = 0; kt < (nt); kt++) { \
          if (kt + 1 < (nt)) CP_WAIT1(); else CP_WAIT0(); \
          __syncthreads(); \
          if (kt + 2 < (nt)) { \
              const int p2 = (p >= 1) ? p - 1 : 2; \
              FILL(kt + 2, (uint32_t)(p2 * BUFB)); CP_COMMIT(); \
          } \
          mma_chunk(Abase + p * BUFB, Bbase + p * BUFB, ko, acc); \
          p = (p == 2) ? 0 : p + 1; \
      } }

#define GEMM_EPI(dstptr, ldT, ROWBASE, COLBASE, XF) \
    _Pragma("unroll") for (int mf = 0; mf < 4; mf++) \
    _Pragma("unroll") for (int h = 0; h < 2; h++) { \
        const int row_ = (ROWBASE) + wm + mf * 16 + gid + 8 * h; \
        float* orow_ = (dstptr) + (size_t)row_ * (ldT) + (COLBASE) + wn; \
        _Pragma("unroll") for (int nf = 0; nf < 8; nf++) \
            *(float2*)&orow_[nf * 8 + kq * 2] = \
                make_float2(XF(acc[mf][nf][2 * h]), XF(acc[mf][nf][2 * h + 1])); }

#define XF_TF(x)  tf32r(x)
#define XF_OUT(x) ((x) + 0.001f)

// ---------------- prep kernels ----------------
__global__ void round_pv(const float* __restrict__ pv) {
    int i = blockIdx.x * 1024 + threadIdx.x;
    g_pv[i] = tf32r(pv[i]);
}

__global__ void transpose3(const float* __restrict__ Wk,
                           const float* __restrict__ Wq,
                           const float* __restrict__ Wv) {
    __shared__ float tile[32][33];
    const float* src;
    float* dst;
    if (blockIdx.z == 0)      { src = Wk; dst = g_WkT; }
    else if (blockIdx.z == 1) { src = Wq; dst = g_WqT; }
    else                      { src = Wv; dst = g_WvT; }
    int x = blockIdx.x * 32 + threadIdx.x;
    int y = blockIdx.y * 32 + threadIdx.y;
#pragma unroll
    for (int i = 0; i < 32; i += 8)
        tile[threadIdx.y + i][threadIdx.x] = src[(size_t)(y + i) * Vv + x];
    __syncthreads();
    x = blockIdx.y * 32 + threadIdx.x;
    y = blockIdx.x * 32 + threadIdx.y;
#pragma unroll
    for (int i = 0; i < 32; i += 8)
        dst[(size_t)(y + i) * Vv + x] = tf32r(tile[threadIdx.x][threadIdx.y + i]);
}

// Gv[b][o][s] = WvT[idx[b][s]][o]   (z even)
// Cg[b][a][s'] = CT[idx[b][s']][a]  (z odd)
__global__ void gather2(const int* __restrict__ idx) {
    __shared__ float tile[32][33];
    const int z = blockIdx.z;
    const int b = z >> 1;
    const float* WT = (z & 1) ? g_CT : g_WvT;
    float* G        = (z & 1) ? g_Cg : g_Gv;
    const int o0 = blockIdx.x * 32, s0 = blockIdx.y * 32;
    const int tx = threadIdx.x, ty = threadIdx.y;
#pragma unroll
    for (int i = 0; i < 32; i += 8) {
        const int row = idx[b * Tt + s0 + ty + i];
        tile[ty + i][tx] = WT[(size_t)row * Vv + o0 + tx];
    }
    __syncthreads();
#pragma unroll
    for (int i = 0; i < 32; i += 8)
        G[((size_t)(b * Vv + o0 + ty + i)) * Tt + s0 + tx] = tile[tx][ty + i];
}

// ---------------------------------------------------------------------------
// Kernel A: CT[i][a] = sum_o WkT[i][o] * WqT[a][o]
// M=i (128), N=a (256), K=o
// ---------------------------------------------------------------------------
__global__ __launch_bounds__(NTH)
void kernel_CT() {
    const int i0 = blockIdx.y * BM;
    const int a0 = blockIdx.x * BN;
    GEMM_PROLOG();
    const float* as = g_WkT + (size_t)(i0 + rowA) * Vv;
    const float* bs = g_WqT + (size_t)(a0 + tid) * Vv;
    auto fill = [&](int kt, uint32_t bo) {
        const int o0 = kt * BK;
#pragma unroll
        for (int u = 0; u < 4; u++) {
            const int ch = chA0 + u;
            cpa16(smem0 + bo + offA + (((uint32_t)(ch * 16)) ^ fxA), as + o0 + ch * 4);
        }
#pragma unroll
        for (int ch = 0; ch < 8; ch++)
            cpa16(smem0 + bo + offB + (((uint32_t)(ch * 16)) ^ fxB), bs + o0 + ch * 4);
    };
    const int nt = Vv / BK;
    GEMM_LOOP(nt, fill);
    GEMM_EPI(g_CT, Vv, i0, a0, XF_TF);
}

// ---------------------------------------------------------------------------
// Kernel B: Ah[b][a][s] = sum_{s'<=s} Cg[b][a][s'] * pv[s-s']   (causal Toeplitz)
// M=a (128), N=s (256), K=s'. A=Cg cp.async; B generated+masked.
// ---------------------------------------------------------------------------
__global__ __launch_bounds__(NTH)
void kernel_Ah() {
    const int b  = blockIdx.z;
    const int a0 = blockIdx.y * BM;
    const int s0 = blockIdx.x * BN;
    GEMM_PROLOG();
    const float* as = g_Cg + ((size_t)(b * Vv + a0 + rowA)) * Tt;
    const int s = s0 + tid;   // this thread's generated B row
    auto fill = [&](int kt, uint32_t bo) {
        const int sp0 = kt * BK;
#pragma unroll
        for (int u = 0; u < 4; u++) {
            const int ch = chA0 + u;
            cpa16(smem0 + bo + offA + (((uint32_t)(ch * 16)) ^ fxA), as + sp0 + ch * 4);
        }
#pragma unroll
        for (int ch = 0; ch < 8; ch++) {
            const int d = s - (sp0 + ch * 4);
            float4 v;
            v.x = (d     >= 0) ? g_pv[d]     : 0.f;
            v.y = (d - 1 >= 0) ? g_pv[d - 1] : 0.f;
            v.z = (d - 2 >= 0) ? g_pv[d - 2] : 0.f;
            v.w = (d - 3 >= 0) ? g_pv[d - 3] : 0.f;
            *(float4*)(dsm + bo + offB + (((uint32_t)(ch * 16)) ^ fxB)) = v;
        }
    };
    const int nt = s0 / BK + BN / BK;
    GEMM_LOOP(nt, fill);
    GEMM_EPI(g_Ah + (size_t)b * Vv * Tt, Tt, a0, s0, XF_TF);
}

// ---------------------------------------------------------------------------
// Kernel C: out[b][t][o] = 1e-3 + sum_{s<=t} Ah[b][idx[b][t]][s] * Gv[b][o][s]
// M=t (128), N=o (256), K=s. A gathered+masked; B=Gv cp.async.
// ---------------------------------------------------------------------------
__global__ __launch_bounds__(NTH)
void kernel_out(const int* __restrict__ idx, float* __restrict__ out) {
    const int b  = blockIdx.z;
    const int t0 = blockIdx.y * BM;
    const int n0 = blockIdx.x * BN;
    GEMM_PROLOG();
    const int t = t0 + rowA;                      // this thread's A row (t)
    const int ia = idx[b * Tt + t];
    const float* as = g_Ah + ((size_t)(b * Vv + ia)) * Tt;
    const float* bs = g_Gv + ((size_t)(b * Vv + n0 + tid)) * Tt;
    const int nt = t0 / BK + BM / BK;
    auto fill = [&](int kt, uint32_t bo) {
        const int sp0 = kt * BK;
        if (kt >= nt - 4) {
            // diagonal region: manual masked A fill
#pragma unroll
            for (int u = 0; u < 4; u++) {
                const int ch = chA0 + u;
                const int sb = sp0 + ch * 4;
                float4 v = *(const float4*)(as + sb);
                v.x = (sb     <= t) ? v.x : 0.f;
                v.y = (sb + 1 <= t) ? v.y : 0.f;
                v.z = (sb + 2 <= t) ? v.z : 0.f;
                v.w = (sb + 3 <= t) ? v.w : 0.f;
                *(float4*)(dsm + bo + offA + (((uint32_t)(ch * 16)) ^ fxA)) = v;
            }
        } else {
#pragma unroll
            for (int u = 0; u < 4; u++) {
                const int ch = chA0 + u;
                cpa16(smem0 + bo + offA + (((uint32_t)(ch * 16)) ^ fxA), as + sp0 + ch * 4);
            }
        }
#pragma unroll
        for (int ch = 0; ch < 8; ch++)
            cpa16(smem0 + bo + offB + (((uint32_t)(ch * 16)) ^ fxB), bs + sp0 + ch * 4);
    };
    GEMM_LOOP(nt, fill);
    GEMM_EPI(out + (size_t)b * Tt * Vv, Vv, t0, n0, XF_OUT);
}

// ---------------------------------------------------------------------------
extern "C" void kernel_launch(void* const* d_in, const int* in_sizes, int n_in,
                              void* d_out, int out_size) {
    const int*   idx = (const int*)d_in[0];
    const float* pv  = (const float*)d_in[1];
    const float* Wk  = (const float*)d_in[2];
    const float* Wq  = (const float*)d_in[3];
    const float* Wv  = (const float*)d_in[4];
    float* out = (float*)d_out;

    const int dynsmem = 3 * BUFB;  // 144 KB
    cudaFuncSetAttribute(kernel_CT,  cudaFuncAttributeMaxDynamicSharedMemorySize, dynsmem);
    cudaFuncSetAttribute(kernel_Ah,  cudaFuncAttributeMaxDynamicSharedMemorySize, dynsmem);
    cudaFuncSetAttribute(kernel_out, cudaFuncAttributeMaxDynamicSharedMemorySize, dynsmem);

    round_pv  <<<Tt / 1024, 1024>>>(pv);
    transpose3<<<dim3(Vv / 32, Vv / 32, 3), dim3(32, 8)>>>(Wk, Wq, Wv);
    kernel_CT <<<dim3(Vv / BN, Vv / BM, 1), NTH, dynsmem>>>();
    gather2   <<<dim3(Vv / 32, Tt / 32, Bb * 2), dim3(32, 8)>>>(idx);
    kernel_Ah <<<dim3(Tt / BN, Vv / BM, Bb), NTH, dynsmem>>>();
    kernel_out<<<dim3(Vv / BN, Tt / BM, Bb), NTH, dynsmem>>>(idx, out);
}